// round 16
// baseline (speedup 1.0000x reference)
#include <cuda_runtime.h>
#include <cuda_fp16.h>
#include <math.h>
#include <stdint.h>

#define Bdim 8
#define Ndim 1024
#define Ddim 1024
#define Hdim 16
#define DEPTH 64
#define MLPdim 4096
#define ROWS 8192
#define EPSLN 1e-6f
#define ISD 0.125f

__device__ float g_ao[ROWS*Ddim];
__device__ float g_attn[Bdim*Hdim*Ndim];
__device__ float g_gq[Bdim*Hdim*DEPTH];
__device__ float g_t[Bdim*Hdim*Ddim];
__device__ float g_h[Bdim*Ddim];
__device__ float g_h2[Bdim*Ddim];
__device__ float g_scale[Bdim*Ddim];
__device__ float g_shift[Bdim*Ddim];
__device__ float g_scale2[Bdim*Ddim];
__device__ float g_shift2[Bdim*Ddim];
__device__ float g_qkvb[3*Ddim];
__device__ float g_wqa[Ddim*Hdim];
__device__ float g_qab[Hdim];
__device__ __half g_xnh[ROWS*Ddim];
__device__ __half g_kh[ROWS*Ddim];
__device__ __half g_vh[ROWS*Ddim];
__device__ __half g_mlph[(size_t)ROWS*MLPdim];
__device__ __half g_wqkv[(size_t)3*Ddim*Ddim];
__device__ __half g_woh[Ddim*Ddim];
__device__ __half g_w1h[(size_t)Ddim*MLPdim];
__device__ __half g_w2h[(size_t)Ddim*MLPdim];

__device__ __forceinline__ uint32_t cvsm(const void* p){
    uint32_t a; asm("{ .reg .u64 t; cvta.to.shared.u64 t, %1; cvt.u32.u64 %0, t; }":"=r"(a):"l"(p)); return a;
}
__device__ __forceinline__ void cp16(uint32_t d, const void* s){
    asm volatile("cp.async.cg.shared.global [%0], [%1], 16;" :: "r"(d), "l"(s));
}
__device__ __forceinline__ void ldsm4(uint32_t* r, uint32_t a){
    asm volatile("ldmatrix.sync.aligned.m8n8.x4.shared.b16 {%0,%1,%2,%3},[%4];"
        : "=r"(r[0]),"=r"(r[1]),"=r"(r[2]),"=r"(r[3]) : "r"(a));
}
__device__ __forceinline__ void mma_f16(float* d, const uint32_t* a, const uint32_t* b){
    asm volatile(
        "mma.sync.aligned.m16n8k16.row.col.f32.f16.f16.f32 "
        "{%0,%1,%2,%3},{%4,%5,%6,%7},{%8,%9},{%0,%1,%2,%3};"
        : "+f"(d[0]), "+f"(d[1]), "+f"(d[2]), "+f"(d[3])
        : "r"(a[0]), "r"(a[1]), "r"(a[2]), "r"(a[3]), "r"(b[0]), "r"(b[1]));
}

// ---------------- fp16 mma GEMM (unchanged) ----------------
#define ROWB 80
#define AB 10240
#define SLOTB 30720
#define NSTAGE 4
#define PIPESM (NSTAGE*SLOTB)

__device__ __forceinline__ void load_stage(uint32_t smb, const __half* A, const __half* Wt,
    int mBase, int nBase, int Ktot, int kB, int slot, int tid){
    uint32_t st = smb + slot*SLOTB;
    #pragma unroll
    for(int i=0;i<2;++i){
        int idx=i*256+tid, row=idx>>2, cc=idx&3;
        cp16(st + row*ROWB + cc*16, A + (size_t)(mBase+row)*Ktot + kB + cc*8);
    }
    #pragma unroll
    for(int i=0;i<4;++i){
        int idx=i*256+tid, row=idx>>2, cc=idx&3;
        cp16(st + AB + row*ROWB + cc*16, Wt + (size_t)(nBase+row)*Ktot + kB + cc*8);
    }
}

template<int EPI>
__global__ __launch_bounds__(256,1)
void hgemm(const __half* __restrict__ A, const __half* __restrict__ Wt,
           const float* __restrict__ bias, const float* __restrict__ res,
           void* __restrict__ Cv, void* __restrict__ C1, void* __restrict__ C2,
           int Ntot, int Ktot, int mOff){
    extern __shared__ char smraw[];
    const uint32_t smb = cvsm(smraw);
    const int tid = threadIdx.x, lane = tid&31, warp = tid>>5;
    const int wm = warp>>2, wn = warp&3, g = lane>>2, c = lane&3;
    const int mBase = mOff + blockIdx.y*128, nBase = blockIdx.x*256;
    const int KS = Ktot/32;

    const uint32_t aoff = (uint32_t)(wm*64 + (lane&15))*ROWB + (uint32_t)(lane>>4)*16;
    const uint32_t boff = AB + (uint32_t)(wn*64 + (lane&7) + ((lane>>4)&1)*8)*ROWB
                          + (uint32_t)((lane>>3)&1)*16;

    float acc[4][8][4];
    #pragma unroll
    for(int i=0;i<4;++i)
        #pragma unroll
        for(int j=0;j<8;++j)
            #pragma unroll
            for(int q=0;q<4;++q) acc[i][j][q]=0.f;

    #pragma unroll
    for(int s=0;s<NSTAGE-1;++s){
        load_stage(smb, A, Wt, mBase, nBase, Ktot, s*32, s, tid);
        asm volatile("cp.async.commit_group;");
    }

    int slot = 0;
    for(int s=0;s<KS;++s){
        asm volatile("cp.async.wait_group %0;" :: "n"(NSTAGE-2));
        __syncthreads();
        const uint32_t sa = smb + (uint32_t)slot*SLOTB;

        uint32_t af[4][4], bf[8][2], bt[4];
        #pragma unroll
        for(int i=0;i<4;++i) ldsm4(af[i], sa + aoff + i*16*ROWB);
        #pragma unroll
        for(int jj=0;jj<4;++jj){
            ldsm4(bt, sa + boff + jj*16*ROWB);
            bf[2*jj][0]=bt[0]; bf[2*jj][1]=bt[1]; bf[2*jj+1][0]=bt[2]; bf[2*jj+1][1]=bt[3];
        }
        if(s+NSTAGE-1<KS){
            int ld = slot+NSTAGE-1; if(ld>=NSTAGE) ld-=NSTAGE;
            load_stage(smb, A, Wt, mBase, nBase, Ktot, (s+NSTAGE-1)*32, ld, tid);
        }
        asm volatile("cp.async.commit_group;");
        #pragma unroll
        for(int i=0;i<4;++i)
            #pragma unroll
            for(int j=0;j<8;++j)
                mma_f16(acc[i][j], af[i], bf[j]);

        #pragma unroll
        for(int i=0;i<4;++i) ldsm4(af[i], sa + aoff + i*16*ROWB + 32);
        #pragma unroll
        for(int jj=0;jj<4;++jj){
            ldsm4(bt, sa + boff + jj*16*ROWB + 32);
            bf[2*jj][0]=bt[0]; bf[2*jj][1]=bt[1]; bf[2*jj+1][0]=bt[2]; bf[2*jj+1][1]=bt[3];
        }
        #pragma unroll
        for(int i=0;i<4;++i)
            #pragma unroll
            for(int j=0;j<8;++j)
                mma_f16(acc[i][j], af[i], bf[j]);

        if(++slot==NSTAGE) slot=0;
    }

    __half* Cq = (__half*)Cv;
    if(EPI==3){
        const int sel = nBase>>10;
        Cq = sel==0 ? (__half*)Cv : (__half*)C1;
    }

    #pragma unroll
    for(int i=0;i<4;++i){
        const int row0 = mBase + wm*64 + i*16 + g;
        #pragma unroll
        for(int j=0;j<8;++j){
            const int colg = nBase + wn*64 + j*8 + 2*c;
            const float b0 = bias[colg], b1 = bias[colg+1];
            #pragma unroll
            for(int half=0;half<2;++half){
                const int row = row0 + half*8;
                float v0 = acc[i][j][half*2+0] + b0;
                float v1 = acc[i][j][half*2+1] + b1;
                if(EPI==1){
                    const size_t off = (size_t)row*Ntot + colg;
                    float* Cf = (float*)Cv;
                    const float2 rr = *reinterpret_cast<const float2*>(res + off);
                    float2 o; o.x = v0+rr.x; o.y = v1+rr.y;
                    *reinterpret_cast<float2*>(Cf + off) = o;
                } else if(EPI==3){
                    const size_t off = (size_t)row*Ddim + (colg&1023);
                    *(__half2*)(Cq + off) = __floats2half2_rn(v0, v1);
                } else {
                    if(EPI==2){
                        v0 = 0.5f*v0*(1.f+erff(v0*0.7071067811865475f));
                        v1 = 0.5f*v1*(1.f+erff(v1*0.7071067811865475f));
                    }
                    const size_t off = (size_t)row*Ntot + colg;
                    *(__half2*)((__half*)Cv + off) = __floats2half2_rn(v0, v1);
                }
            }
        }
    }
}

__global__ __launch_bounds__(256)
void trh(const float* __restrict__ in, __half* __restrict__ out, int K, int N){
    __shared__ float t[32][33];
    const int n0 = blockIdx.x*32, k0 = blockIdx.y*32;
    const int tx = threadIdx.x & 31, ty = threadIdx.x >> 5;
    #pragma unroll
    for(int i=0;i<32;i+=8)
        t[ty+i][tx] = in[(size_t)(k0+ty+i)*N + n0+tx];
    __syncthreads();
    #pragma unroll
    for(int i=0;i<32;i+=8)
        out[(size_t)(n0+ty+i)*K + k0+tx] = __float2half_rn(t[tx][ty+i]);
}

__global__ void concat3(const float* __restrict__ a, const float* __restrict__ b,
                        const float* __restrict__ c, float* __restrict__ o){
    const int i = blockIdx.x*256+threadIdx.x;
    o[i] = (i<1024) ? a[i] : ((i<2048) ? b[i-1024] : c[i-2048]);
}

// wqa[k,h] = dot(wq_w[k,:], qa_w[:,h]); qab[h] = dot(wq_b, qa_w[:,h]) + qa_b[h]
__global__ __launch_bounds__(256)
void qaw_fuse(const float* __restrict__ wq_w, const float* __restrict__ qa_w,
              const float* __restrict__ wq_b, const float* __restrict__ qa_b,
              float* __restrict__ wqa, float* __restrict__ qab){
    const int gi = blockIdx.x*8 + (threadIdx.x>>5);
    const int lane = threadIdx.x&31;
    if(gi >= 16400) return;
    const int h = gi&15, k = gi>>4;
    const float* src = (k<1024) ? wq_w + (size_t)k*Ddim : wq_b;
    float acc = 0.f;
    #pragma unroll 4
    for(int j=lane;j<Ddim;j+=32) acc = fmaf(src[j], qa_w[j*Hdim+h], acc);
    #pragma unroll
    for(int o=16;o;o>>=1) acc += __shfl_xor_sync(~0u,acc,o);
    if(lane==0){
        if(k<1024) wqa[k*Hdim+h] = acc;
        else qab[h] = acc + qa_b[h];
    }
}

__device__ __forceinline__ float bsum(float v, float* sm){
    #pragma unroll
    for(int o=16;o;o>>=1) v += __shfl_xor_sync(~0u,v,o);
    int wd=threadIdx.x>>5;
    if((threadIdx.x&31)==0) sm[wd]=v;
    __syncthreads();
    float r=0.f;
    if(threadIdx.x<8){ r=sm[threadIdx.x];
        #pragma unroll
        for(int o=4;o;o>>=1) r += __shfl_xor_sync(0xFFu,r,o);
        if(threadIdx.x==0) sm[0]=r; }
    __syncthreads(); r=sm[0]; __syncthreads(); return r;
}
__device__ __forceinline__ float bmax(float v, float* sm){
    #pragma unroll
    for(int o=16;o;o>>=1) v = fmaxf(v,__shfl_xor_sync(~0u,v,o));
    int wd=threadIdx.x>>5;
    if((threadIdx.x&31)==0) sm[wd]=v;
    __syncthreads();
    float r=-1e30f;
    if(threadIdx.x<8){ r=sm[threadIdx.x];
        #pragma unroll
        for(int o=4;o;o>>=1) r = fmaxf(r,__shfl_xor_sync(0xFFu,r,o));
        if(threadIdx.x==0) sm[0]=r; }
    __syncthreads(); r=sm[0]; __syncthreads(); return r;
}

__global__ __launch_bounds__(256)
void ln_mod(const float* __restrict__ x, const float* __restrict__ sc,
            const float* __restrict__ sh, __half* __restrict__ out, int rOff){
    __shared__ float sm[8];
    const int row=rOff+blockIdx.x, b=row>>10, n=row&1023;
    float4 v = reinterpret_cast<const float4*>(x+(size_t)row*Ddim)[threadIdx.x];
    float mean = bsum(v.x+v.y+v.z+v.w, sm)*(1.f/Ddim);
    float dx=v.x-mean, dy=v.y-mean, dz=v.z-mean, dw=v.w-mean;
    float var = bsum(dx*dx+dy*dy+dz*dz+dw*dw, sm)*(1.f/Ddim);
    float rs = rsqrtf(var+EPSLN);
    float s = sc[b*Ddim+n]*rs, t = sh[b*Ddim+n];
    __half2* o = reinterpret_cast<__half2*>(out+(size_t)row*Ddim) + threadIdx.x*2;
    o[0] = __floats2half2_rn(dx*s+t, dy*s+t);
    o[1] = __floats2half2_rn(dz*s+t, dw*s+t);
}

__global__ __launch_bounds__(256)
void small_gemm(const float* __restrict__ A, const float* __restrict__ W,
                const float* __restrict__ bias, float* __restrict__ out, int act){
    const int n = blockIdx.x*256+threadIdx.x, b = blockIdx.y;
    const float* a = A+(size_t)b*Ddim;
    float acc=0.f;
    for(int k=0;k<Ddim;++k) acc = fmaf(a[k], W[(size_t)k*Ddim+n], acc);
    acc += bias[n];
    if(act) acc = fmaxf(acc,0.f);
    out[(size_t)b*Ddim+n]=acc;
}

__global__ __launch_bounds__(256)
void cond2(const float* __restrict__ hb,
           const float* __restrict__ W0, const float* __restrict__ b0, float* __restrict__ o0,
           const float* __restrict__ W1, const float* __restrict__ b1, float* __restrict__ o1){
    const float* W = blockIdx.z ? W1 : W0;
    const float* bi = blockIdx.z ? b1 : b0;
    float* o = blockIdx.z ? o1 : o0;
    const int n = blockIdx.x*256+threadIdx.x, b = blockIdx.y;
    const float* a = hb+(size_t)b*Ddim;
    float acc=0.f;
    for(int k=0;k<Ddim;++k) acc = fmaf(a[k], W[(size_t)k*Ddim+n], acc);
    o[(size_t)b*Ddim+n] = acc + bi[n];
}

// attn logits from xnh: attn[b,h,n] = (xnh[bn,:] @ wqa[:,h] + qab[h]) * ISD
__global__ __launch_bounds__(256)
void qa2_kernel(const __half* __restrict__ xn, const float* __restrict__ wqa,
                const float* __restrict__ qab, float* __restrict__ attn){
    const int warp=threadIdx.x>>5, lane=threadIdx.x&31;
    const int gi=blockIdx.x*8+warp, hh=gi&15, bn=gi>>4;
    const __half* xr = xn+(size_t)bn*Ddim;
    float acc=0.f;
    #pragma unroll 4
    for(int k=lane;k<Ddim;k+=32) acc = fmaf(__half2float(xr[k]), wqa[k*Hdim+hh], acc);
    #pragma unroll
    for(int o=16;o;o>>=1) acc += __shfl_xor_sync(~0u,acc,o);
    if(lane==0){
        const int b=bn>>10, n=bn&1023;
        attn[(size_t)b*Hdim*Ndim + hh*Ndim + n] = (acc+qab[hh])*ISD;
    }
}

__global__ __launch_bounds__(256)
void softmax_kernel(float* __restrict__ attn, float* __restrict__ oa){
    __shared__ float sm[8];
    const int row=blockIdx.x;
    float4 v = reinterpret_cast<float4*>(attn+(size_t)row*Ndim)[threadIdx.x];
    float m = bmax(fmaxf(fmaxf(v.x,v.y),fmaxf(v.z,v.w)), sm);
    v.x=__expf(v.x-m); v.y=__expf(v.y-m); v.z=__expf(v.z-m); v.w=__expf(v.w-m);
    float s = bsum(v.x+v.y+v.z+v.w, sm);
    const float inv=1.f/s;
    v.x*=inv; v.y*=inv; v.z*=inv; v.w*=inv;
    reinterpret_cast<float4*>(attn+(size_t)row*Ndim)[threadIdx.x]=v;
    reinterpret_cast<float4*>(oa+(size_t)row*Ndim)[threadIdx.x]=v;
}

// t[bh,:] = sum_n attn[bh,n] * xn[b,n,:]   (grid: (h=16, b=8), 256 thr, 4 floats/thr)
__global__ __launch_bounds__(256)
void tmix_kernel(const float* __restrict__ attn, const __half* __restrict__ xn,
                 float* __restrict__ t){
    const int h = blockIdx.x, b = blockIdx.y;
    const float* ar = attn + (size_t)(b*Hdim+h)*Ndim;
    const __half2* xp = reinterpret_cast<const __half2*>(xn + (size_t)b*Ndim*Ddim);
    const int d2 = threadIdx.x;
    float a0=0.f,a1=0.f,a2=0.f,a3=0.f;
    for(int n=0;n<Ndim;++n){
        const float a = ar[n];
        float2 x0 = __half22float2(xp[(size_t)n*512 + d2]);
        float2 x1 = __half22float2(xp[(size_t)n*512 + 256 + d2]);
        a0=fmaf(a,x0.x,a0); a1=fmaf(a,x0.y,a1); a2=fmaf(a,x1.x,a2); a3=fmaf(a,x1.y,a3);
    }
    float* tr = t + (size_t)(b*Hdim+h)*Ddim;
    tr[2*d2]=a0; tr[2*d2+1]=a1; tr[512+2*d2]=a2; tr[512+2*d2+1]=a3;
}

// gq[bh*64+d] = dot(t[bh,:], wqt[h*64+d,:]) + wq_b[h*64+d]
__global__ __launch_bounds__(256)
void gq2_kernel(const float* __restrict__ t, const __half* __restrict__ wqt,
                const float* __restrict__ wq_b, float* __restrict__ gq){
    const int warp=threadIdx.x>>5, lane=threadIdx.x&31;
    const int gi=blockIdx.x*8+warp;     // 0..8191
    const int bh=gi>>6, d=gi&63, hh=bh&15;
    const float* tr = t + (size_t)bh*Ddim;
    const __half* wr = wqt + (size_t)(hh*DEPTH+d)*Ddim;
    float acc=0.f;
    #pragma unroll 4
    for(int k=lane;k<Ddim;k+=32) acc = fmaf(tr[k], __half2float(wr[k]), acc);
    #pragma unroll
    for(int o=16;o;o>>=1) acc += __shfl_xor_sync(~0u,acc,o);
    if(lane==0) gq[gi] = acc + wq_b[hh*DEPTH+d];
}

__global__ __launch_bounds__(256)
void r_kernel(const float* __restrict__ gq, const __half* __restrict__ k,
              __half* __restrict__ v){
    const size_t i = (size_t)blockIdx.x*256+threadIdx.x;
    const int d=(int)(i&1023), b=(int)(i>>20);
    v[i] = __float2half_rn(gq[b*Ddim+d]*__half2float(k[i])*__half2float(v[i]));
}

#define SYMF(p,s) float* p; cudaGetSymbolAddress((void**)&p, s);
#define SYMH(p,s) __half* p; cudaGetSymbolAddress((void**)&p, s);

extern "C" void kernel_launch(void* const* d_in, const int* in_sizes, int n_in,
                              void* d_out, int out_size){
    const float* inputs=(const float*)d_in[0];
    const float* z=(const float*)d_in[1];
    const float *n1_hw=(const float*)d_in[2], *n1_hb=(const float*)d_in[3];
    const float *n1_gw=(const float*)d_in[4], *n1_gb=(const float*)d_in[5];
    const float *n1_bw=(const float*)d_in[6], *n1_bb=(const float*)d_in[7];
    const float *wq_w=(const float*)d_in[8],  *wq_b=(const float*)d_in[9];
    const float *wk_w=(const float*)d_in[10], *wk_b=(const float*)d_in[11];
    const float *wv_w=(const float*)d_in[12], *wv_b=(const float*)d_in[13];
    const float *qa_w=(const float*)d_in[14], *qa_b=(const float*)d_in[15];
    const float *out_w=(const float*)d_in[16],*out_b=(const float*)d_in[17];
    const float *n2_hw=(const float*)d_in[18],*n2_hb=(const float*)d_in[19];
    const float *n2_gw=(const float*)d_in[20],*n2_gb=(const float*)d_in[21];
    const float *n2_bw=(const float*)d_in[22],*n2_bb=(const float*)d_in[23];
    const float *mw1=(const float*)d_in[24],  *mb1=(const float*)d_in[25];
    const float *mw2=(const float*)d_in[26],  *mb2=(const float*)d_in[27];

    float* out=(float*)d_out;
    float* out_attn = out + (size_t)ROWS*Ddim;

    SYMF(ao,g_ao) SYMF(attn,g_attn) SYMF(gq,g_gq) SYMF(tbuf,g_t)
    SYMF(hbuf,g_h) SYMF(hbuf2,g_h2)
    SYMF(sc,g_scale) SYMF(sh,g_shift) SYMF(sc2,g_scale2) SYMF(sh2,g_shift2)
    SYMF(qkvb,g_qkvb) SYMF(wqa,g_wqa) SYMF(qab,g_qab)
    SYMH(xnh,g_xnh) SYMH(kh,g_kh) SYMH(vh,g_vh) SYMH(mlph,g_mlph)
    SYMH(wqkv,g_wqkv) SYMH(woh,g_woh) SYMH(w1h,g_w1h) SYMH(w2h,g_w2h)

    cudaFuncSetAttribute(hgemm<1>, cudaFuncAttributeMaxDynamicSharedMemorySize, PIPESM);
    cudaFuncSetAttribute(hgemm<2>, cudaFuncAttributeMaxDynamicSharedMemorySize, PIPESM);
    cudaFuncSetAttribute(hgemm<3>, cudaFuncAttributeMaxDynamicSharedMemorySize, PIPESM);

    cudaStream_t sB, sC, sD;
    cudaStreamCreateWithFlags(&sB, cudaStreamNonBlocking);
    cudaStreamCreateWithFlags(&sC, cudaStreamNonBlocking);
    cudaStreamCreateWithFlags(&sD, cudaStreamNonBlocking);
    cudaEvent_t eFork, eB, eC, eLN1, eKV, eR, eE;
    cudaEventCreateWithFlags(&eFork, cudaEventDisableTiming);
    cudaEventCreateWithFlags(&eB, cudaEventDisableTiming);
    cudaEventCreateWithFlags(&eC, cudaEventDisableTiming);
    cudaEventCreateWithFlags(&eLN1, cudaEventDisableTiming);
    cudaEventCreateWithFlags(&eKV, cudaEventDisableTiming);
    cudaEventCreateWithFlags(&eR, cudaEventDisableTiming);
    cudaEventCreateWithFlags(&eE, cudaEventDisableTiming);

    cudaEventRecord(eFork, 0);
    cudaStreamWaitEvent(sB, eFork, 0);
    cudaStreamWaitEvent(sC, eFork, 0);

    // stream B: weight preprocessing + qa fusion
    trh<<<dim3(32,32),256,0,sB>>>(wq_w, wqkv, Ddim, Ddim);            // wq^T for gq2
    trh<<<dim3(32,32),256,0,sB>>>(wk_w, wqkv + (size_t)Ddim*Ddim, Ddim, Ddim);
    trh<<<dim3(32,32),256,0,sB>>>(wv_w, wqkv + (size_t)2*Ddim*Ddim, Ddim, Ddim);
    trh<<<dim3(32,32),256,0,sB>>>(out_w, woh, Ddim, Ddim);
    trh<<<dim3(128,32),256,0,sB>>>(mw1, w1h, Ddim, MLPdim);
    trh<<<dim3(32,128),256,0,sB>>>(mw2, w2h, MLPdim, Ddim);
    concat3<<<12,256,0,sB>>>(wq_b, wk_b, wv_b, qkvb);
    qaw_fuse<<<2050,256,0,sB>>>(wq_w, qa_w, wq_b, qa_b, wqa, qab);
    cudaEventRecord(eB, sB);

    // stream C: norm2 conditioning
    small_gemm<<<dim3(4,Bdim),256,0,sC>>>(z, n2_hw, n2_hb, hbuf2, 1);
    cond2<<<dim3(4,Bdim,2),256,0,sC>>>(hbuf2, n2_gw, n2_gb, sc2, n2_bw, n2_bb, sh2);
    cudaEventRecord(eC, sC);

    // main: norm1 conditioning + ln1
    small_gemm<<<dim3(4,Bdim),256>>>(z, n1_hw, n1_hb, hbuf, 1);
    cond2<<<dim3(4,Bdim,2),256>>>(hbuf, n1_gw, n1_gb, sc, n1_bw, n1_bb, sh);
    ln_mod<<<ROWS,256>>>(inputs, sc, sh, xnh, 0);
    cudaEventRecord(eLN1, 0);
    cudaStreamWaitEvent(0, eB, 0);

    // stream D: kv GEMM (k,v only; dual output)
    cudaStreamWaitEvent(sD, eLN1, 0);
    cudaStreamWaitEvent(sD, eB, 0);
    hgemm<3><<<dim3(8,64),256,PIPESM,sD>>>(xnh, wqkv + (size_t)Ddim*Ddim, qkvb + Ddim,
                                           nullptr, kh, vh, nullptr, 2048, Ddim, 0);
    cudaEventRecord(eKV, sD);

    // main: attention chain without q (overlaps kv GEMM)
    qa2_kernel<<<ROWS*Hdim/8,256>>>(xnh, wqa, qab, attn);
    softmax_kernel<<<Bdim*Hdim,256>>>(attn, out_attn);
    tmix_kernel<<<dim3(Hdim,Bdim),256>>>(attn, xnh, tbuf);
    gq2_kernel<<<ROWS/8,256>>>(tbuf, wqkv, wq_b, gq);

    cudaStreamWaitEvent(0, eKV, 0);
    r_kernel<<<(size_t)ROWS*Ddim/256,256>>>(gq, kh, vh);
    cudaEventRecord(eR, 0);

    // post-attention chain split by M-halves
    cudaStreamWaitEvent(sD, eR, 0);
    cudaStreamWaitEvent(sD, eC, 0);
    cudaStreamWaitEvent(0, eC, 0);

    hgemm<1><<<dim3(4,32),256,PIPESM>>>(vh, woh, out_b, inputs, ao, nullptr, nullptr, Ddim, Ddim, 0);
    ln_mod<<<4096,256>>>(ao, sc2, sh2, xnh, 0);
    hgemm<2><<<dim3(16,32),256,PIPESM>>>(xnh, w1h, mb1, nullptr, mlph, nullptr, nullptr, MLPdim, Ddim, 0);
    hgemm<1><<<dim3(4,32),256,PIPESM>>>(mlph, w2h, mb2, ao, out, nullptr, nullptr, Ddim, MLPdim, 0);

    hgemm<1><<<dim3(4,32),256,PIPESM,sD>>>(vh, woh, out_b, inputs, ao, nullptr, nullptr, Ddim, Ddim, 4096);
    ln_mod<<<4096,256,0,sD>>>(ao, sc2, sh2, xnh, 4096);
    hgemm<2><<<dim3(16,32),256,PIPESM,sD>>>(xnh, w1h, mb1, nullptr, mlph, nullptr, nullptr, MLPdim, Ddim, 4096);
    hgemm<1><<<dim3(4,32),256,PIPESM,sD>>>(mlph, w2h, mb2, ao, out, nullptr, nullptr, Ddim, MLPdim, 4096);
    cudaEventRecord(eE, sD);
    cudaStreamWaitEvent(0, eE, 0);

    cudaEventDestroy(eFork); cudaEventDestroy(eB); cudaEventDestroy(eC);
    cudaEventDestroy(eLN1); cudaEventDestroy(eKV); cudaEventDestroy(eR); cudaEventDestroy(eE);
    cudaStreamDestroy(sB); cudaStreamDestroy(sC); cudaStreamDestroy(sD);
}

// round 17
// speedup vs baseline: 1.0327x; 1.0327x over previous
#include <cuda_runtime.h>
#include <cuda_fp16.h>
#include <math.h>
#include <stdint.h>

#define Bdim 8
#define Ndim 1024
#define Ddim 1024
#define Hdim 16
#define DEPTH 64
#define MLPdim 4096
#define ROWS 8192
#define EPSLN 1e-6f
#define ISD 0.125f

__device__ float g_ao[ROWS*Ddim];
__device__ float g_attn[Bdim*Hdim*Ndim];
__device__ float g_gq[Bdim*Hdim*DEPTH];
__device__ float g_t[Bdim*Hdim*Ddim];
__device__ float g_h[Bdim*Ddim];
__device__ float g_h2[Bdim*Ddim];
__device__ float g_scale[Bdim*Ddim];
__device__ float g_shift[Bdim*Ddim];
__device__ float g_scale2[Bdim*Ddim];
__device__ float g_shift2[Bdim*Ddim];
__device__ float g_qkvb[3*Ddim];
__device__ float g_wqa[Ddim*Hdim];
__device__ float g_qab[Hdim];
__device__ __half g_xnh[ROWS*Ddim];
__device__ __half g_kh[ROWS*Ddim];
__device__ __half g_vh[ROWS*Ddim];
__device__ __half g_mlph[(size_t)ROWS*MLPdim];
__device__ __half g_wqkv[(size_t)3*Ddim*Ddim];
__device__ __half g_woh[Ddim*Ddim];
__device__ __half g_w1h[(size_t)Ddim*MLPdim];
__device__ __half g_w2h[(size_t)Ddim*MLPdim];

__device__ __forceinline__ uint32_t cvsm(const void* p){
    uint32_t a; asm("{ .reg .u64 t; cvta.to.shared.u64 t, %1; cvt.u32.u64 %0, t; }":"=r"(a):"l"(p)); return a;
}
__device__ __forceinline__ void cp16(uint32_t d, const void* s){
    asm volatile("cp.async.cg.shared.global [%0], [%1], 16;" :: "r"(d), "l"(s));
}
__device__ __forceinline__ void ldsm4(uint32_t* r, uint32_t a){
    asm volatile("ldmatrix.sync.aligned.m8n8.x4.shared.b16 {%0,%1,%2,%3},[%4];"
        : "=r"(r[0]),"=r"(r[1]),"=r"(r[2]),"=r"(r[3]) : "r"(a));
}
__device__ __forceinline__ void mma_f16(float* d, const uint32_t* a, const uint32_t* b){
    asm volatile(
        "mma.sync.aligned.m16n8k16.row.col.f32.f16.f16.f32 "
        "{%0,%1,%2,%3},{%4,%5,%6,%7},{%8,%9},{%0,%1,%2,%3};"
        : "+f"(d[0]), "+f"(d[1]), "+f"(d[2]), "+f"(d[3])
        : "r"(a[0]), "r"(a[1]), "r"(a[2]), "r"(a[3]), "r"(b[0]), "r"(b[1]));
}

// ---------------- fp16 mma GEMM (unchanged) ----------------
#define ROWB 80
#define AB 10240
#define SLOTB 30720
#define NSTAGE 4
#define PIPESM (NSTAGE*SLOTB)

__device__ __forceinline__ void load_stage(uint32_t smb, const __half* A, const __half* Wt,
    int mBase, int nBase, int Ktot, int kB, int slot, int tid){
    uint32_t st = smb + slot*SLOTB;
    #pragma unroll
    for(int i=0;i<2;++i){
        int idx=i*256+tid, row=idx>>2, cc=idx&3;
        cp16(st + row*ROWB + cc*16, A + (size_t)(mBase+row)*Ktot + kB + cc*8);
    }
    #pragma unroll
    for(int i=0;i<4;++i){
        int idx=i*256+tid, row=idx>>2, cc=idx&3;
        cp16(st + AB + row*ROWB + cc*16, Wt + (size_t)(nBase+row)*Ktot + kB + cc*8);
    }
}

template<int EPI>
__global__ __launch_bounds__(256,1)
void hgemm(const __half* __restrict__ A, const __half* __restrict__ Wt,
           const float* __restrict__ bias, const float* __restrict__ res,
           void* __restrict__ Cv, void* __restrict__ C1, void* __restrict__ C2,
           int Ntot, int Ktot, int mOff){
    extern __shared__ char smraw[];
    const uint32_t smb = cvsm(smraw);
    const int tid = threadIdx.x, lane = tid&31, warp = tid>>5;
    const int wm = warp>>2, wn = warp&3, g = lane>>2, c = lane&3;
    const int mBase = mOff + blockIdx.y*128, nBase = blockIdx.x*256;
    const int KS = Ktot/32;

    const uint32_t aoff = (uint32_t)(wm*64 + (lane&15))*ROWB + (uint32_t)(lane>>4)*16;
    const uint32_t boff = AB + (uint32_t)(wn*64 + (lane&7) + ((lane>>4)&1)*8)*ROWB
                          + (uint32_t)((lane>>3)&1)*16;

    float acc[4][8][4];
    #pragma unroll
    for(int i=0;i<4;++i)
        #pragma unroll
        for(int j=0;j<8;++j)
            #pragma unroll
            for(int q=0;q<4;++q) acc[i][j][q]=0.f;

    #pragma unroll
    for(int s=0;s<NSTAGE-1;++s){
        load_stage(smb, A, Wt, mBase, nBase, Ktot, s*32, s, tid);
        asm volatile("cp.async.commit_group;");
    }

    int slot = 0;
    for(int s=0;s<KS;++s){
        asm volatile("cp.async.wait_group %0;" :: "n"(NSTAGE-2));
        __syncthreads();
        const uint32_t sa = smb + (uint32_t)slot*SLOTB;

        uint32_t af[4][4], bf[8][2], bt[4];
        #pragma unroll
        for(int i=0;i<4;++i) ldsm4(af[i], sa + aoff + i*16*ROWB);
        #pragma unroll
        for(int jj=0;jj<4;++jj){
            ldsm4(bt, sa + boff + jj*16*ROWB);
            bf[2*jj][0]=bt[0]; bf[2*jj][1]=bt[1]; bf[2*jj+1][0]=bt[2]; bf[2*jj+1][1]=bt[3];
        }
        if(s+NSTAGE-1<KS){
            int ld = slot+NSTAGE-1; if(ld>=NSTAGE) ld-=NSTAGE;
            load_stage(smb, A, Wt, mBase, nBase, Ktot, (s+NSTAGE-1)*32, ld, tid);
        }
        asm volatile("cp.async.commit_group;");
        #pragma unroll
        for(int i=0;i<4;++i)
            #pragma unroll
            for(int j=0;j<8;++j)
                mma_f16(acc[i][j], af[i], bf[j]);

        #pragma unroll
        for(int i=0;i<4;++i) ldsm4(af[i], sa + aoff + i*16*ROWB + 32);
        #pragma unroll
        for(int jj=0;jj<4;++jj){
            ldsm4(bt, sa + boff + jj*16*ROWB + 32);
            bf[2*jj][0]=bt[0]; bf[2*jj][1]=bt[1]; bf[2*jj+1][0]=bt[2]; bf[2*jj+1][1]=bt[3];
        }
        #pragma unroll
        for(int i=0;i<4;++i)
            #pragma unroll
            for(int j=0;j<8;++j)
                mma_f16(acc[i][j], af[i], bf[j]);

        if(++slot==NSTAGE) slot=0;
    }

    __half* Cq = (__half*)Cv;
    if(EPI==3){
        const int sel = nBase>>10;
        Cq = sel==0 ? (__half*)Cv : (__half*)C1;
    }

    #pragma unroll
    for(int i=0;i<4;++i){
        const int row0 = mBase + wm*64 + i*16 + g;
        #pragma unroll
        for(int j=0;j<8;++j){
            const int colg = nBase + wn*64 + j*8 + 2*c;
            const float b0 = bias[colg], b1 = bias[colg+1];
            #pragma unroll
            for(int half=0;half<2;++half){
                const int row = row0 + half*8;
                float v0 = acc[i][j][half*2+0] + b0;
                float v1 = acc[i][j][half*2+1] + b1;
                if(EPI==1){
                    const size_t off = (size_t)row*Ntot + colg;
                    float* Cf = (float*)Cv;
                    const float2 rr = *reinterpret_cast<const float2*>(res + off);
                    float2 o; o.x = v0+rr.x; o.y = v1+rr.y;
                    *reinterpret_cast<float2*>(Cf + off) = o;
                } else if(EPI==3){
                    const size_t off = (size_t)row*Ddim + (colg&1023);
                    *(__half2*)(Cq + off) = __floats2half2_rn(v0, v1);
                } else {
                    if(EPI==2){
                        v0 = 0.5f*v0*(1.f+erff(v0*0.7071067811865475f));
                        v1 = 0.5f*v1*(1.f+erff(v1*0.7071067811865475f));
                    }
                    const size_t off = (size_t)row*Ntot + colg;
                    *(__half2*)((__half*)Cv + off) = __floats2half2_rn(v0, v1);
                }
            }
        }
    }
}

__global__ __launch_bounds__(256)
void trh(const float* __restrict__ in, __half* __restrict__ out, int K, int N){
    __shared__ float t[32][33];
    const int n0 = blockIdx.x*32, k0 = blockIdx.y*32;
    const int tx = threadIdx.x & 31, ty = threadIdx.x >> 5;
    #pragma unroll
    for(int i=0;i<32;i+=8)
        t[ty+i][tx] = in[(size_t)(k0+ty+i)*N + n0+tx];
    __syncthreads();
    #pragma unroll
    for(int i=0;i<32;i+=8)
        out[(size_t)(n0+ty+i)*K + k0+tx] = __float2half_rn(t[tx][ty+i]);
}

__global__ void concat3(const float* __restrict__ a, const float* __restrict__ b,
                        const float* __restrict__ c, float* __restrict__ o){
    const int i = blockIdx.x*256+threadIdx.x;
    o[i] = (i<1024) ? a[i] : ((i<2048) ? b[i-1024] : c[i-2048]);
}

__global__ __launch_bounds__(256)
void qaw_fuse(const float* __restrict__ wq_w, const float* __restrict__ qa_w,
              const float* __restrict__ wq_b, const float* __restrict__ qa_b,
              float* __restrict__ wqa, float* __restrict__ qab){
    const int gi = blockIdx.x*8 + (threadIdx.x>>5);
    const int lane = threadIdx.x&31;
    if(gi >= 16400) return;
    const int h = gi&15, k = gi>>4;
    const float* src = (k<1024) ? wq_w + (size_t)k*Ddim : wq_b;
    float acc = 0.f;
    #pragma unroll 4
    for(int j=lane;j<Ddim;j+=32) acc = fmaf(src[j], qa_w[j*Hdim+h], acc);
    #pragma unroll
    for(int o=16;o;o>>=1) acc += __shfl_xor_sync(~0u,acc,o);
    if(lane==0){
        if(k<1024) wqa[k*Hdim+h] = acc;
        else qab[h] = acc + qa_b[h];
    }
}

__device__ __forceinline__ float bsum(float v, float* sm){
    #pragma unroll
    for(int o=16;o;o>>=1) v += __shfl_xor_sync(~0u,v,o);
    int wd=threadIdx.x>>5;
    if((threadIdx.x&31)==0) sm[wd]=v;
    __syncthreads();
    float r=0.f;
    if(threadIdx.x<8){ r=sm[threadIdx.x];
        #pragma unroll
        for(int o=4;o;o>>=1) r += __shfl_xor_sync(0xFFu,r,o);
        if(threadIdx.x==0) sm[0]=r; }
    __syncthreads(); r=sm[0]; __syncthreads(); return r;
}
__device__ __forceinline__ float bmax(float v, float* sm){
    #pragma unroll
    for(int o=16;o;o>>=1) v = fmaxf(v,__shfl_xor_sync(~0u,v,o));
    int wd=threadIdx.x>>5;
    if((threadIdx.x&31)==0) sm[wd]=v;
    __syncthreads();
    float r=-1e30f;
    if(threadIdx.x<8){ r=sm[threadIdx.x];
        #pragma unroll
        for(int o=4;o;o>>=1) r = fmaxf(r,__shfl_xor_sync(0xFFu,r,o));
        if(threadIdx.x==0) sm[0]=r; }
    __syncthreads(); r=sm[0]; __syncthreads(); return r;
}

__global__ __launch_bounds__(256)
void ln_mod(const float* __restrict__ x, const float* __restrict__ sc,
            const float* __restrict__ sh, __half* __restrict__ out, int rOff){
    __shared__ float sm[8];
    const int row=rOff+blockIdx.x, b=row>>10, n=row&1023;
    float4 v = reinterpret_cast<const float4*>(x+(size_t)row*Ddim)[threadIdx.x];
    float mean = bsum(v.x+v.y+v.z+v.w, sm)*(1.f/Ddim);
    float dx=v.x-mean, dy=v.y-mean, dz=v.z-mean, dw=v.w-mean;
    float var = bsum(dx*dx+dy*dy+dz*dz+dw*dw, sm)*(1.f/Ddim);
    float rs = rsqrtf(var+EPSLN);
    float s = sc[b*Ddim+n]*rs, t = sh[b*Ddim+n];
    __half2* o = reinterpret_cast<__half2*>(out+(size_t)row*Ddim) + threadIdx.x*2;
    o[0] = __floats2half2_rn(dx*s+t, dy*s+t);
    o[1] = __floats2half2_rn(dz*s+t, dw*s+t);
}

__global__ __launch_bounds__(256)
void small_gemm(const float* __restrict__ A, const float* __restrict__ W,
                const float* __restrict__ bias, float* __restrict__ out, int act){
    const int n = blockIdx.x*256+threadIdx.x, b = blockIdx.y;
    const float* a = A+(size_t)b*Ddim;
    float acc=0.f;
    for(int k=0;k<Ddim;++k) acc = fmaf(a[k], W[(size_t)k*Ddim+n], acc);
    acc += bias[n];
    if(act) acc = fmaxf(acc,0.f);
    out[(size_t)b*Ddim+n]=acc;
}

__global__ __launch_bounds__(256)
void cond2(const float* __restrict__ hb,
           const float* __restrict__ W0, const float* __restrict__ b0, float* __restrict__ o0,
           const float* __restrict__ W1, const float* __restrict__ b1, float* __restrict__ o1){
    const float* W = blockIdx.z ? W1 : W0;
    const float* bi = blockIdx.z ? b1 : b0;
    float* o = blockIdx.z ? o1 : o0;
    const int n = blockIdx.x*256+threadIdx.x, b = blockIdx.y;
    const float* a = hb+(size_t)b*Ddim;
    float acc=0.f;
    for(int k=0;k<Ddim;++k) acc = fmaf(a[k], W[(size_t)k*Ddim+n], acc);
    o[(size_t)b*Ddim+n] = acc + bi[n];
}

__global__ __launch_bounds__(256)
void qa2_kernel(const __half* __restrict__ xn, const float* __restrict__ wqa,
                const float* __restrict__ qab, float* __restrict__ attn){
    const int warp=threadIdx.x>>5, lane=threadIdx.x&31;
    const int gi=blockIdx.x*8+warp, hh=gi&15, bn=gi>>4;
    const __half* xr = xn+(size_t)bn*Ddim;
    float acc=0.f;
    #pragma unroll 4
    for(int k=lane;k<Ddim;k+=32) acc = fmaf(__half2float(xr[k]), wqa[k*Hdim+hh], acc);
    #pragma unroll
    for(int o=16;o;o>>=1) acc += __shfl_xor_sync(~0u,acc,o);
    if(lane==0){
        const int b=bn>>10, n=bn&1023;
        attn[(size_t)b*Hdim*Ndim + hh*Ndim + n] = (acc+qab[hh])*ISD;
    }
}

__global__ __launch_bounds__(256)
void softmax_kernel(float* __restrict__ attn, float* __restrict__ oa){
    __shared__ float sm[8];
    const int row=blockIdx.x;
    float4 v = reinterpret_cast<float4*>(attn+(size_t)row*Ndim)[threadIdx.x];
    float m = bmax(fmaxf(fmaxf(v.x,v.y),fmaxf(v.z,v.w)), sm);
    v.x=__expf(v.x-m); v.y=__expf(v.y-m); v.z=__expf(v.z-m); v.w=__expf(v.w-m);
    float s = bsum(v.x+v.y+v.z+v.w, sm);
    const float inv=1.f/s;
    v.x*=inv; v.y*=inv; v.z*=inv; v.w*=inv;
    reinterpret_cast<float4*>(attn+(size_t)row*Ndim)[threadIdx.x]=v;
    reinterpret_cast<float4*>(oa+(size_t)row*Ndim)[threadIdx.x]=v;
}

// t[b,h,:] = sum_n attn[b,h,n]*xn[b,n,:]; one pass over xn per (b, 128-col chunk).
// grid (8 chunks, 8 b), 256 thr: thread = (d2 = t&63 → half2 col, hg = t>>6 → 4 heads)
// dyn smem: attn[b] 16x1024 f32 = 64KB
__global__ __launch_bounds__(256)
void tmix_kernel(const float* __restrict__ attn, const __half* __restrict__ xn,
                 float* __restrict__ t){
    extern __shared__ float sa[];
    const int chunk = blockIdx.x, b = blockIdx.y;
    const int d2 = threadIdx.x & 63, hg = threadIdx.x >> 6;
    // load attn[b] into smem (16384 floats, float4 per thread x16)
    const float4* ap = reinterpret_cast<const float4*>(attn + (size_t)b*Hdim*Ndim);
    #pragma unroll
    for(int i=0;i<16;++i)
        reinterpret_cast<float4*>(sa)[i*256 + threadIdx.x] = ap[i*256 + threadIdx.x];
    __syncthreads();
    const __half2* xp = reinterpret_cast<const __half2*>(xn + (size_t)b*Ndim*Ddim)
                        + chunk*64 + d2;
    float a0[4], a1[4];
    #pragma unroll
    for(int i=0;i<4;++i){ a0[i]=0.f; a1[i]=0.f; }
    for(int n=0;n<Ndim;++n){
        float2 x = __half22float2(xp[(size_t)n*512]);
        #pragma unroll
        for(int i=0;i<4;++i){
            const float a = sa[(hg*4+i)*Ndim + n];
            a0[i] = fmaf(a, x.x, a0[i]);
            a1[i] = fmaf(a, x.y, a1[i]);
        }
    }
    #pragma unroll
    for(int i=0;i<4;++i){
        float* tr = t + (size_t)(b*Hdim + hg*4 + i)*Ddim + chunk*128 + 2*d2;
        tr[0]=a0[i]; tr[1]=a1[i];
    }
}

// gq[bh*64+d] = dot(t[bh,:], wqt[h*64+d,:]) + wq_b[h*64+d]
__global__ __launch_bounds__(256)
void gq2_kernel(const float* __restrict__ t, const __half* __restrict__ wqt,
                const float* __restrict__ wq_b, float* __restrict__ gq){
    const int warp=threadIdx.x>>5, lane=threadIdx.x&31;
    const int gi=blockIdx.x*8+warp;
    const int bh=gi>>6, d=gi&63, hh=bh&15;
    const float* tr = t + (size_t)bh*Ddim;
    const __half* wr = wqt + (size_t)(hh*DEPTH+d)*Ddim;
    float acc=0.f;
    #pragma unroll 4
    for(int k=lane;k<Ddim;k+=32) acc = fmaf(tr[k], __half2float(wr[k]), acc);
    #pragma unroll
    for(int o=16;o;o>>=1) acc += __shfl_xor_sync(~0u,acc,o);
    if(lane==0) gq[gi] = acc + wq_b[hh*DEPTH+d];
}

__global__ __launch_bounds__(256)
void r_kernel(const float* __restrict__ gq, const __half* __restrict__ k,
              __half* __restrict__ v){
    const size_t i = (size_t)blockIdx.x*256+threadIdx.x;
    const int d=(int)(i&1023), b=(int)(i>>20);
    v[i] = __float2half_rn(gq[b*Ddim+d]*__half2float(k[i])*__half2float(v[i]));
}

#define SYMF(p,s) float* p; cudaGetSymbolAddress((void**)&p, s);
#define SYMH(p,s) __half* p; cudaGetSymbolAddress((void**)&p, s);

extern "C" void kernel_launch(void* const* d_in, const int* in_sizes, int n_in,
                              void* d_out, int out_size){
    const float* inputs=(const float*)d_in[0];
    const float* z=(const float*)d_in[1];
    const float *n1_hw=(const float*)d_in[2], *n1_hb=(const float*)d_in[3];
    const float *n1_gw=(const float*)d_in[4], *n1_gb=(const float*)d_in[5];
    const float *n1_bw=(const float*)d_in[6], *n1_bb=(const float*)d_in[7];
    const float *wq_w=(const float*)d_in[8],  *wq_b=(const float*)d_in[9];
    const float *wk_w=(const float*)d_in[10], *wk_b=(const float*)d_in[11];
    const float *wv_w=(const float*)d_in[12], *wv_b=(const float*)d_in[13];
    const float *qa_w=(const float*)d_in[14], *qa_b=(const float*)d_in[15];
    const float *out_w=(const float*)d_in[16],*out_b=(const float*)d_in[17];
    const float *n2_hw=(const float*)d_in[18],*n2_hb=(const float*)d_in[19];
    const float *n2_gw=(const float*)d_in[20],*n2_gb=(const float*)d_in[21];
    const float *n2_bw=(const float*)d_in[22],*n2_bb=(const float*)d_in[23];
    const float *mw1=(const float*)d_in[24],  *mb1=(const float*)d_in[25];
    const float *mw2=(const float*)d_in[26],  *mb2=(const float*)d_in[27];

    float* out=(float*)d_out;
    float* out_attn = out + (size_t)ROWS*Ddim;

    SYMF(ao,g_ao) SYMF(attn,g_attn) SYMF(gq,g_gq) SYMF(tbuf,g_t)
    SYMF(hbuf,g_h) SYMF(hbuf2,g_h2)
    SYMF(sc,g_scale) SYMF(sh,g_shift) SYMF(sc2,g_scale2) SYMF(sh2,g_shift2)
    SYMF(qkvb,g_qkvb) SYMF(wqa,g_wqa) SYMF(qab,g_qab)
    SYMH(xnh,g_xnh) SYMH(kh,g_kh) SYMH(vh,g_vh) SYMH(mlph,g_mlph)
    SYMH(wqkv,g_wqkv) SYMH(woh,g_woh) SYMH(w1h,g_w1h) SYMH(w2h,g_w2h)

    cudaFuncSetAttribute(hgemm<1>, cudaFuncAttributeMaxDynamicSharedMemorySize, PIPESM);
    cudaFuncSetAttribute(hgemm<2>, cudaFuncAttributeMaxDynamicSharedMemorySize, PIPESM);
    cudaFuncSetAttribute(hgemm<3>, cudaFuncAttributeMaxDynamicSharedMemorySize, PIPESM);
    cudaFuncSetAttribute(tmix_kernel, cudaFuncAttributeMaxDynamicSharedMemorySize, 65536);

    cudaStream_t sB, sC, sD;
    cudaStreamCreateWithFlags(&sB, cudaStreamNonBlocking);
    cudaStreamCreateWithFlags(&sC, cudaStreamNonBlocking);
    cudaStreamCreateWithFlags(&sD, cudaStreamNonBlocking);
    cudaEvent_t eFork, eB, eC, eLN1, eKV, eR, eE;
    cudaEventCreateWithFlags(&eFork, cudaEventDisableTiming);
    cudaEventCreateWithFlags(&eB, cudaEventDisableTiming);
    cudaEventCreateWithFlags(&eC, cudaEventDisableTiming);
    cudaEventCreateWithFlags(&eLN1, cudaEventDisableTiming);
    cudaEventCreateWithFlags(&eKV, cudaEventDisableTiming);
    cudaEventCreateWithFlags(&eR, cudaEventDisableTiming);
    cudaEventCreateWithFlags(&eE, cudaEventDisableTiming);

    cudaEventRecord(eFork, 0);
    cudaStreamWaitEvent(sB, eFork, 0);
    cudaStreamWaitEvent(sC, eFork, 0);

    // stream B: weight preprocessing + qa fusion
    trh<<<dim3(32,32),256,0,sB>>>(wq_w, wqkv, Ddim, Ddim);
    trh<<<dim3(32,32),256,0,sB>>>(wk_w, wqkv + (size_t)Ddim*Ddim, Ddim, Ddim);
    trh<<<dim3(32,32),256,0,sB>>>(wv_w, wqkv + (size_t)2*Ddim*Ddim, Ddim, Ddim);
    trh<<<dim3(32,32),256,0,sB>>>(out_w, woh, Ddim, Ddim);
    trh<<<dim3(128,32),256,0,sB>>>(mw1, w1h, Ddim, MLPdim);
    trh<<<dim3(32,128),256,0,sB>>>(mw2, w2h, MLPdim, Ddim);
    concat3<<<12,256,0,sB>>>(wq_b, wk_b, wv_b, qkvb);
    qaw_fuse<<<2050,256,0,sB>>>(wq_w, qa_w, wq_b, qa_b, wqa, qab);
    cudaEventRecord(eB, sB);

    // stream C: norm2 conditioning
    small_gemm<<<dim3(4,Bdim),256,0,sC>>>(z, n2_hw, n2_hb, hbuf2, 1);
    cond2<<<dim3(4,Bdim,2),256,0,sC>>>(hbuf2, n2_gw, n2_gb, sc2, n2_bw, n2_bb, sh2);
    cudaEventRecord(eC, sC);

    // main: norm1 conditioning + ln1
    small_gemm<<<dim3(4,Bdim),256>>>(z, n1_hw, n1_hb, hbuf, 1);
    cond2<<<dim3(4,Bdim,2),256>>>(hbuf, n1_gw, n1_gb, sc, n1_bw, n1_bb, sh);
    ln_mod<<<ROWS,256>>>(inputs, sc, sh, xnh, 0);
    cudaEventRecord(eLN1, 0);
    cudaStreamWaitEvent(0, eB, 0);

    // stream D: kv GEMM
    cudaStreamWaitEvent(sD, eLN1, 0);
    cudaStreamWaitEvent(sD, eB, 0);
    hgemm<3><<<dim3(8,64),256,PIPESM,sD>>>(xnh, wqkv + (size_t)Ddim*Ddim, qkvb + Ddim,
                                           nullptr, kh, vh, nullptr, 2048, Ddim, 0);
    cudaEventRecord(eKV, sD);

    // main: attention chain (no q GEMM), overlaps kv GEMM
    qa2_kernel<<<ROWS*Hdim/8,256>>>(xnh, wqa, qab, attn);
    softmax_kernel<<<Bdim*Hdim,256>>>(attn, out_attn);
    tmix_kernel<<<dim3(8,Bdim),256,65536>>>(attn, xnh, tbuf);
    gq2_kernel<<<ROWS/8,256>>>(tbuf, wqkv, wq_b, gq);

    cudaStreamWaitEvent(0, eKV, 0);
    r_kernel<<<(size_t)ROWS*Ddim/256,256>>>(gq, kh, vh);
    cudaEventRecord(eR, 0);

    // post-attention chain split by M-halves
    cudaStreamWaitEvent(sD, eR, 0);
    cudaStreamWaitEvent(sD, eC, 0);
    cudaStreamWaitEvent(0, eC, 0);

    hgemm<1><<<dim3(4,32),256,PIPESM>>>(vh, woh, out_b, inputs, ao, nullptr, nullptr, Ddim, Ddim, 0);
    ln_mod<<<4096,256>>>(ao, sc2, sh2, xnh, 0);
    hgemm<2><<<dim3(16,32),256,PIPESM>>>(xnh, w1h, mb1, nullptr, mlph, nullptr, nullptr, MLPdim, Ddim, 0);
    hgemm<1><<<dim3(4,32),256,PIPESM>>>(mlph, w2h, mb2, ao, out, nullptr, nullptr, Ddim, MLPdim, 0);

    hgemm<1><<<dim3(4,32),256,PIPESM,sD>>>(vh, woh, out_b, inputs, ao, nullptr, nullptr, Ddim, Ddim, 4096);
    ln_mod<<<4096,256,0,sD>>>(ao, sc2, sh2, xnh, 4096);
    hgemm<2><<<dim3(16,32),256,PIPESM,sD>>>(xnh, w1h, mb1, nullptr, mlph, nullptr, nullptr, MLPdim, Ddim, 4096);
    hgemm<1><<<dim3(4,32),256,PIPESM,sD>>>(mlph, w2h, mb2, ao, out, nullptr, nullptr, Ddim, MLPdim, 4096);
    cudaEventRecord(eE, sD);
    cudaStreamWaitEvent(0, eE, 0);

    cudaEventDestroy(eFork); cudaEventDestroy(eB); cudaEventDestroy(eC);
    cudaEventDestroy(eLN1); cudaEventDestroy(eKV); cudaEventDestroy(eR); cudaEventDestroy(eE);
    cudaStreamDestroy(sB); cudaStreamDestroy(sC); cudaStreamDestroy(sD);
}